// round 2
// baseline (speedup 1.0000x reference)
#include <cuda_runtime.h>

#define BB   4
#define TT   4096
#define NINN 256
#define DD   64

// Scratch for projected Q, K, V: [B*T, 64] each (4 MB each).
__device__ float g_Q[BB * TT * DD];
__device__ float g_K[BB * TT * DD];
__device__ float g_V[BB * TT * DD];

// ---------------------------------------------------------------------------
// Kernel 1: QKV projection.  grid=(256,3), block=256.
// Each block computes a 64-row x 64-col tile of (y @ W) for one of Wq/Wk/Wv.
// K-loop tiled by 64 through shared memory; 4x4 register micro-tile/thread.
// ---------------------------------------------------------------------------
__global__ __launch_bounds__(256) void qkv_kernel(
    const float* __restrict__ y,
    const float* __restrict__ Wq,
    const float* __restrict__ Wk,
    const float* __restrict__ Wv)
{
    __shared__ float sy[64 * 68];   // 64 rows x 64 k, stride 68 (bank-safe)
    __shared__ float sw[64 * 64];   // 64 k x 64 cols

    const float* W;
    float* outp;
    if (blockIdx.y == 0)      { W = Wq; outp = g_Q; }
    else if (blockIdx.y == 1) { W = Wk; outp = g_K; }
    else                      { W = Wv; outp = g_V; }

    const int row0 = blockIdx.x * 64;
    const int tid  = threadIdx.x;
    const int tx   = tid & 15;   // col group (4 cols)
    const int ty   = tid >> 4;   // row group (4 rows)

    float acc[4][4];
#pragma unroll
    for (int i = 0; i < 4; i++)
#pragma unroll
        for (int j = 0; j < 4; j++) acc[i][j] = 0.f;

    for (int kt = 0; kt < NINN; kt += 64) {
        for (int i = tid; i < 1024; i += 256) {
            const int r = i >> 4, g = i & 15;
            *(float4*)&sy[r * 68 + g * 4] =
                *(const float4*)&y[(size_t)(row0 + r) * NINN + kt + g * 4];
            *(float4*)&sw[r * 64 + g * 4] =
                *(const float4*)&W[(size_t)(kt + r) * DD + g * 4];
        }
        __syncthreads();

#pragma unroll 8
        for (int k = 0; k < 64; k++) {
            const float a0 = sy[(ty * 4 + 0) * 68 + k];
            const float a1 = sy[(ty * 4 + 1) * 68 + k];
            const float a2 = sy[(ty * 4 + 2) * 68 + k];
            const float a3 = sy[(ty * 4 + 3) * 68 + k];
            const float4 b4 = *(const float4*)&sw[k * 64 + tx * 4];
            acc[0][0] += a0 * b4.x; acc[0][1] += a0 * b4.y; acc[0][2] += a0 * b4.z; acc[0][3] += a0 * b4.w;
            acc[1][0] += a1 * b4.x; acc[1][1] += a1 * b4.y; acc[1][2] += a1 * b4.z; acc[1][3] += a1 * b4.w;
            acc[2][0] += a2 * b4.x; acc[2][1] += a2 * b4.y; acc[2][2] += a2 * b4.z; acc[2][3] += a2 * b4.w;
            acc[3][0] += a3 * b4.x; acc[3][1] += a3 * b4.y; acc[3][2] += a3 * b4.z; acc[3][3] += a3 * b4.w;
        }
        __syncthreads();
    }

#pragma unroll
    for (int i = 0; i < 4; i++) {
        float4 v;
        v.x = acc[i][0]; v.y = acc[i][1]; v.z = acc[i][2]; v.w = acc[i][3];
        *(float4*)&outp[(size_t)(row0 + ty * 4 + i) * DD + tx * 4] = v;
    }
}

// ---------------------------------------------------------------------------
// Kernel 2: causal flash attention.  grid=256 (B=4 x 64 q-tiles), block=128.
// BM=BN=64, D=64.  Thread (qg, c): owns query rows q=2*qg, 2*qg+1 in the
// score stage (16 j's at c*16), and dim chunk [c*16, c*16+16) in PV.
// Online softmax with a per-row-pair shared running max (valid; l per row).
// K rows rotated, V columns XOR-swizzled for conflict-free smem reads.
// Heavy q-tiles scheduled first (causal work is proportional to qt).
// ---------------------------------------------------------------------------
__global__ __launch_bounds__(128) void attn_kernel(float* __restrict__ out)
{
    extern __shared__ float sm[];
    float* Qs = sm;                 // 64 x stride 68
    float* Ks = sm + 64 * 68;       // 64 x stride 68, row-rotated
    float* Vs = sm + 2 * 64 * 68;   // 64 x stride 68, col-xor-swizzled
    float* Ps = sm + 3 * 64 * 68;   // 64 x stride 69

    const int tid = threadIdx.x;
    const int b   = blockIdx.x & 3;
    const int qt  = 63 - (blockIdx.x >> 2);   // heavy tiles first
    const int q0  = qt * 64;
    const int c   = tid & 3;
    const int qg  = tid >> 2;
    const int q   = qg * 2;

    const float* Qg = g_Q + (size_t)(b * TT + q0) * DD;
    for (int i = tid; i < 1024; i += 128) {
        const int r = i >> 4, g = i & 15;
        *(float4*)&Qs[r * 68 + g * 4] = *(const float4*)&Qg[r * DD + g * 4];
    }
    // covered by the __syncthreads() after the first K/V tile load

    float o0[16], o1[16];
#pragma unroll
    for (int i = 0; i < 16; i++) { o0[i] = 0.f; o1[i] = 0.f; }
    float m = -1e30f, l0 = 0.f, l1 = 0.f;

    for (int t = 0; t <= qt; t++) {
        const int k0 = t * 64;
        const float* Kg = g_K + (size_t)(b * TT + k0) * DD;
        const float* Vg = g_V + (size_t)(b * TT + k0) * DD;
        for (int i = tid; i < 1024; i += 128) {
            const int r = i >> 4, g = i & 15;
            const int kp = (g + 2 * ((r >> 4) & 3)) & 15;   // K row rotation
            *(float4*)&Ks[r * 68 + kp * 4] = *(const float4*)&Kg[r * DD + g * 4];
            const int vp = g ^ ((g >> 2) & 3);              // V col xor-swizzle
            *(float4*)&Vs[r * 68 + vp * 4] = *(const float4*)&Vg[r * DD + g * 4];
        }
        __syncthreads();

        // --- scores: S[q..q+1][c*16 .. c*16+15] ---
        float s0[16], s1[16];
#pragma unroll
        for (int i = 0; i < 16; i++) { s0[i] = 0.f; s1[i] = 0.f; }
        const float4* Qv0 = (const float4*)(Qs + q * 68);
        const float4* Qv1 = (const float4*)(Qs + (q + 1) * 68);
#pragma unroll 4
        for (int d4 = 0; d4 < 16; d4++) {
            const float4 a0 = Qv0[d4];
            const float4 a1 = Qv1[d4];
            const int kp = (d4 + 2 * c) & 15;   // row-rotation: rows c*16+jj all rotated by 2c
            const float* Kbase = Ks + (c * 16) * 68 + kp * 4;
#pragma unroll
            for (int jj = 0; jj < 16; jj++) {
                const float4 bb = *(const float4*)(Kbase + jj * 68);
                s0[jj] += a0.x * bb.x; s0[jj] += a0.y * bb.y;
                s0[jj] += a0.z * bb.z; s0[jj] += a0.w * bb.w;
                s1[jj] += a1.x * bb.x; s1[jj] += a1.y * bb.y;
                s1[jj] += a1.z * bb.z; s1[jj] += a1.w * bb.w;
            }
        }

        const float scale = 0.125f;  // 1/sqrt(64)
        const bool diag = (t == qt);
        float tmax = -1e30f;
#pragma unroll
        for (int jj = 0; jj < 16; jj++) {
            const int j = c * 16 + jj;
            float v0 = s0[jj] * scale;
            float v1 = s1[jj] * scale;
            if (diag) {
                if (j > q)     v0 = -1e30f;
                if (j > q + 1) v1 = -1e30f;
            }
            s0[jj] = v0; s1[jj] = v1;
            tmax = fmaxf(tmax, fmaxf(v0, v1));
        }
        tmax = fmaxf(tmax, __shfl_xor_sync(0xffffffffu, tmax, 1));
        tmax = fmaxf(tmax, __shfl_xor_sync(0xffffffffu, tmax, 2));

        const float m_new = fmaxf(m, tmax);
        const float corr  = __expf(m - m_new);
        float ls0 = 0.f, ls1 = 0.f;
#pragma unroll
        for (int jj = 0; jj < 16; jj++) {
            const float p0 = __expf(s0[jj] - m_new);
            const float p1 = __expf(s1[jj] - m_new);
            Ps[q * 69 + c * 16 + jj]       = p0;
            Ps[(q + 1) * 69 + c * 16 + jj] = p1;
            ls0 += p0; ls1 += p1;
        }
        ls0 += __shfl_xor_sync(0xffffffffu, ls0, 1);
        ls0 += __shfl_xor_sync(0xffffffffu, ls0, 2);
        ls1 += __shfl_xor_sync(0xffffffffu, ls1, 1);
        ls1 += __shfl_xor_sync(0xffffffffu, ls1, 2);
        l0 = l0 * corr + ls0;
        l1 = l1 * corr + ls1;
        m = m_new;
#pragma unroll
        for (int i = 0; i < 16; i++) { o0[i] *= corr; o1[i] *= corr; }
        __syncthreads();

        // --- PV: accumulate O[q..q+1][c*16 .. c*16+15] ---
#pragma unroll 2
        for (int j = 0; j < 64; j++) {
            const float p0 = Ps[q * 69 + j];
            const float p1 = Ps[(q + 1) * 69 + j];
#pragma unroll
            for (int k = 0; k < 4; k++) {
                const int g  = c * 4 + k;
                const int vp = g ^ ((g >> 2) & 3);
                const float4 vv = *(const float4*)(Vs + j * 68 + vp * 4);
                o0[k * 4 + 0] += p0 * vv.x; o0[k * 4 + 1] += p0 * vv.y;
                o0[k * 4 + 2] += p0 * vv.z; o0[k * 4 + 3] += p0 * vv.w;
                o1[k * 4 + 0] += p1 * vv.x; o1[k * 4 + 1] += p1 * vv.y;
                o1[k * 4 + 2] += p1 * vv.z; o1[k * 4 + 3] += p1 * vv.w;
            }
        }
        __syncthreads();
    }

    const float inv0 = 1.f / l0;
    const float inv1 = 1.f / l1;
    float* O0 = out + (size_t)(b * TT + q0 + q) * DD + c * 16;
    float* O1 = O0 + DD;
#pragma unroll
    for (int k = 0; k < 4; k++) {
        float4 v0, v1;
        v0.x = o0[k * 4 + 0] * inv0; v0.y = o0[k * 4 + 1] * inv0;
        v0.z = o0[k * 4 + 2] * inv0; v0.w = o0[k * 4 + 3] * inv0;
        v1.x = o1[k * 4 + 0] * inv1; v1.y = o1[k * 4 + 1] * inv1;
        v1.z = o1[k * 4 + 2] * inv1; v1.w = o1[k * 4 + 3] * inv1;
        *(float4*)&O0[k * 4] = v0;
        *(float4*)&O1[k * 4] = v1;
    }
}

// ---------------------------------------------------------------------------
extern "C" void kernel_launch(void* const* d_in, const int* in_sizes, int n_in,
                              void* d_out, int out_size)
{
    (void)in_sizes; (void)n_in; (void)out_size;
    const float* y  = (const float*)d_in[0];
    const float* Wq = (const float*)d_in[1];
    const float* Wk = (const float*)d_in[2];
    const float* Wv = (const float*)d_in[3];

    qkv_kernel<<<dim3((BB * TT) / 64, 3), 256>>>(y, Wq, Wk, Wv);

    const int smem_bytes = (3 * 64 * 68 + 64 * 69) * (int)sizeof(float);  // 69888
    cudaFuncSetAttribute(attn_kernel,
                         cudaFuncAttributeMaxDynamicSharedMemorySize, smem_bytes);
    attn_kernel<<<BB * (TT / 64), 128, smem_bytes>>>((float*)d_out);
}

// round 4
// speedup vs baseline: 1.2942x; 1.2942x over previous
#include <cuda_runtime.h>

#define BB   4
#define TT   4096
#define NINN 256
#define DD   64

// Scratch for projected Q, K, V: [B*T, 64] each (4 MB each).
__device__ float g_Q[BB * TT * DD];
__device__ float g_K[BB * TT * DD];
__device__ float g_V[BB * TT * DD];

// ---- packed f32x2 helpers (sm_103a paired fp32; ptxas won't emit from C++) ----
#define FFMA2(d, a, b) asm("fma.rn.f32x2 %0, %1, %2, %0;" : "+l"(d) : "l"(a), "l"(b))
#define MUL2(d, a)     asm("mul.rn.f32x2 %0, %0, %1;"     : "+l"(d) : "l"(a))

__device__ __forceinline__ unsigned long long pack2(float a, float b) {
    unsigned long long r;
    asm("mov.b64 %0, {%1, %2};" : "=l"(r) : "f"(a), "f"(b));
    return r;
}
__device__ __forceinline__ float2 unpack2(unsigned long long v) {
    float2 r;
    asm("mov.b64 {%0, %1}, %2;" : "=f"(r.x), "=f"(r.y) : "l"(v));
    return r;
}

// ---------------------------------------------------------------------------
// Kernel 1: QKV projection.  grid=(256,3), block=256. (passed; unchanged)
// ---------------------------------------------------------------------------
__global__ __launch_bounds__(256) void qkv_kernel(
    const float* __restrict__ y,
    const float* __restrict__ Wq,
    const float* __restrict__ Wk,
    const float* __restrict__ Wv)
{
    __shared__ float sy[64 * 68];
    __shared__ float sw[64 * 64];

    const float* W;
    float* outp;
    if (blockIdx.y == 0)      { W = Wq; outp = g_Q; }
    else if (blockIdx.y == 1) { W = Wk; outp = g_K; }
    else                      { W = Wv; outp = g_V; }

    const int row0 = blockIdx.x * 64;
    const int tid  = threadIdx.x;
    const int tx   = tid & 15;
    const int ty   = tid >> 4;

    float acc[4][4];
#pragma unroll
    for (int i = 0; i < 4; i++)
#pragma unroll
        for (int j = 0; j < 4; j++) acc[i][j] = 0.f;

    for (int kt = 0; kt < NINN; kt += 64) {
        for (int i = tid; i < 1024; i += 256) {
            const int r = i >> 4, g = i & 15;
            *(float4*)&sy[r * 68 + g * 4] =
                *(const float4*)&y[(size_t)(row0 + r) * NINN + kt + g * 4];
            *(float4*)&sw[r * 64 + g * 4] =
                *(const float4*)&W[(size_t)(kt + r) * DD + g * 4];
        }
        __syncthreads();

#pragma unroll 8
        for (int k = 0; k < 64; k++) {
            const float a0 = sy[(ty * 4 + 0) * 68 + k];
            const float a1 = sy[(ty * 4 + 1) * 68 + k];
            const float a2 = sy[(ty * 4 + 2) * 68 + k];
            const float a3 = sy[(ty * 4 + 3) * 68 + k];
            const float4 b4 = *(const float4*)&sw[k * 64 + tx * 4];
            acc[0][0] += a0 * b4.x; acc[0][1] += a0 * b4.y; acc[0][2] += a0 * b4.z; acc[0][3] += a0 * b4.w;
            acc[1][0] += a1 * b4.x; acc[1][1] += a1 * b4.y; acc[1][2] += a1 * b4.z; acc[1][3] += a1 * b4.w;
            acc[2][0] += a2 * b4.x; acc[2][1] += a2 * b4.y; acc[2][2] += a2 * b4.z; acc[2][3] += a2 * b4.w;
            acc[3][0] += a3 * b4.x; acc[3][1] += a3 * b4.y; acc[3][2] += a3 * b4.z; acc[3][3] += a3 * b4.w;
        }
        __syncthreads();
    }

#pragma unroll
    for (int i = 0; i < 4; i++) {
        float4 v;
        v.x = acc[i][0]; v.y = acc[i][1]; v.z = acc[i][2]; v.w = acc[i][3];
        *(float4*)&outp[(size_t)(row0 + ty * 4 + i) * DD + tx * 4] = v;
    }
}

// ---------------------------------------------------------------------------
// Kernel 2: causal flash attention.  grid=256 (B=4 x 64 q-tiles), block=256.
// BM=BN=64, D=64.  Thread (qg, c) with qg=tid>>4, c=tid&15:
//   owns query rows qg*4..qg*4+3 and score j-chunk c*4..c*4+3,
//   and in PV the dim chunk c*4..c*4+3.
// All dot products run on the paired-fp32 pipe (fma.rn.f32x2), pairing the
// two halves of each float4 along the reduction dim (lo/hi partial sums,
// one horizontal add per score at the epilogue; zero packing in QK^T).
// Layouts (all stride 68): Q identity, K rotated by row>>2, V identity,
// P row-major (float4 stores along j; broadcast scalar loads in PV).
// All smem access patterns hit each 16B bank-quad exactly twice per warp
// instruction = conflict-free at the 128B/cyc crossbar floor.
// ---------------------------------------------------------------------------
__global__ __launch_bounds__(256, 2) void attn_kernel(float* __restrict__ out)
{
    extern __shared__ float sm[];
    float* Qs = sm;                 // 64 x 68
    float* Ks = sm + 64 * 68;       // 64 x 68, col group rotated by (row>>2)
    float* Vs = sm + 2 * 64 * 68;   // 64 x 68
    float* Ps = sm + 3 * 64 * 68;   // 64 x 68

    const int tid = threadIdx.x;
    const int b   = blockIdx.x & 3;
    const int qt  = 63 - (blockIdx.x >> 2);   // heavy q-tiles first
    const int q0  = qt * 64;
    const int c   = tid & 15;
    const int qg  = tid >> 4;

    // load Q tile (synced by the barrier after the first K/V load)
    const float* Qg = g_Q + (size_t)(b * TT + q0) * DD;
    for (int i = tid; i < 1024; i += 256) {
        const int r = i >> 4, g = i & 15;
        *(float4*)&Qs[r * 68 + g * 4] = *(const float4*)&Qg[r * DD + g * 4];
    }

    unsigned long long o2[4][2];
#pragma unroll
    for (int qi = 0; qi < 4; qi++) { o2[qi][0] = 0ull; o2[qi][1] = 0ull; }
    float m[4], l[4];
#pragma unroll
    for (int qi = 0; qi < 4; qi++) { m[qi] = -1e30f; l[qi] = 0.f; }

    for (int t = 0; t <= qt; t++) {
        const float* Kg = g_K + (size_t)(b * TT + t * 64) * DD;
        const float* Vg = g_V + (size_t)(b * TT + t * 64) * DD;
        for (int i = tid; i < 1024; i += 256) {
            const int r = i >> 4, g = i & 15;
            const int kp = (g + (r >> 2)) & 15;           // K rotation
            *(float4*)&Ks[r * 68 + kp * 4] = *(const float4*)&Kg[r * DD + g * 4];
            *(float4*)&Vs[r * 68 + g * 4]  = *(const float4*)&Vg[r * DD + g * 4];
        }
        __syncthreads();

        // --- scores: S[qg*4+qi][c*4+jj], paired over the d dimension ---
        unsigned long long s2[4][4];
#pragma unroll
        for (int qi = 0; qi < 4; qi++)
#pragma unroll
            for (int jj = 0; jj < 4; jj++) s2[qi][jj] = 0ull;

#pragma unroll 4
        for (int d4 = 0; d4 < 16; d4++) {
            ulonglong2 q2[4], k2[4];
#pragma unroll
            for (int qi = 0; qi < 4; qi++)
                q2[qi] = *(const ulonglong2*)(Qs + (qg * 4 + qi) * 68 + d4 * 4);
            const int kc = ((d4 + c) & 15) * 4;
#pragma unroll
            for (int jj = 0; jj < 4; jj++)
                k2[jj] = *(const ulonglong2*)(Ks + (c * 4 + jj) * 68 + kc);
#pragma unroll
            for (int qi = 0; qi < 4; qi++)
#pragma unroll
                for (int jj = 0; jj < 4; jj++) {
                    FFMA2(s2[qi][jj], q2[qi].x, k2[jj].x);
                    FFMA2(s2[qi][jj], q2[qi].y, k2[jj].y);
                }
        }

        // --- softmax epilogue (online, per q-row; reductions over the 16 c's) ---
        const bool diag = (t == qt);
        float s[4][4];
#pragma unroll
        for (int qi = 0; qi < 4; qi++)
#pragma unroll
            for (int jj = 0; jj < 4; jj++) {
                const float2 h = unpack2(s2[qi][jj]);
                float v = (h.x + h.y) * 0.125f;           // 1/sqrt(64)
                if (diag && (c * 4 + jj > qg * 4 + qi)) v = -1e30f;
                s[qi][jj] = v;
            }

#pragma unroll
        for (int qi = 0; qi < 4; qi++) {
            float tm = fmaxf(fmaxf(s[qi][0], s[qi][1]), fmaxf(s[qi][2], s[qi][3]));
#pragma unroll
            for (int w = 1; w < 16; w <<= 1)
                tm = fmaxf(tm, __shfl_xor_sync(0xffffffffu, tm, w));
            const float m_new = fmaxf(m[qi], tm);
            const float corr  = __expf(m[qi] - m_new);
            m[qi] = m_new;

            float p0 = __expf(s[qi][0] - m_new);
            float p1 = __expf(s[qi][1] - m_new);
            float p2 = __expf(s[qi][2] - m_new);
            float p3 = __expf(s[qi][3] - m_new);
            float4 pv; pv.x = p0; pv.y = p1; pv.z = p2; pv.w = p3;
            *(float4*)&Ps[(qg * 4 + qi) * 68 + c * 4] = pv;

            float ls = p0 + p1 + p2 + p3;
#pragma unroll
            for (int w = 1; w < 16; w <<= 1)
                ls += __shfl_xor_sync(0xffffffffu, ls, w);
            l[qi] = l[qi] * corr + ls;

            const unsigned long long c2 = pack2(corr, corr);
            MUL2(o2[qi][0], c2);
            MUL2(o2[qi][1], c2);
        }
        __syncthreads();

        // --- PV: O[qg*4+qi][c*4 .. c*4+3] += P V ---
#pragma unroll 4
        for (int j = 0; j < 64; j++) {
            const ulonglong2 v2 = *(const ulonglong2*)(Vs + j * 68 + c * 4);
#pragma unroll
            for (int qi = 0; qi < 4; qi++) {
                const float p = Ps[(qg * 4 + qi) * 68 + j];
                const unsigned long long pd = pack2(p, p);
                FFMA2(o2[qi][0], pd, v2.x);
                FFMA2(o2[qi][1], pd, v2.y);
            }
        }
        __syncthreads();
    }

#pragma unroll
    for (int qi = 0; qi < 4; qi++) {
        const float inv = 1.f / l[qi];
        const float2 a = unpack2(o2[qi][0]);
        const float2 bqd = unpack2(o2[qi][1]);
        float4 v;
        v.x = a.x * inv; v.y = a.y * inv; v.z = bqd.x * inv; v.w = bqd.y * inv;
        *(float4*)&out[(size_t)(b * TT + q0 + qg * 4 + qi) * DD + c * 4] = v;
    }
}

// ---------------------------------------------------------------------------
extern "C" void kernel_launch(void* const* d_in, const int* in_sizes, int n_in,
                              void* d_out, int out_size)
{
    (void)in_sizes; (void)n_in; (void)out_size;
    const float* y  = (const float*)d_in[0];
    const float* Wq = (const float*)d_in[1];
    const float* Wk = (const float*)d_in[2];
    const float* Wv = (const float*)d_in[3];

    qkv_kernel<<<dim3((BB * TT) / 64, 3), 256>>>(y, Wq, Wk, Wv);

    const int smem_bytes = 4 * 64 * 68 * (int)sizeof(float);  // 69632
    cudaFuncSetAttribute(attn_kernel,
                         cudaFuncAttributeMaxDynamicSharedMemorySize, smem_bytes);
    attn_kernel<<<BB * (TT / 64), 256, smem_bytes>>>((float*)d_out);
}

// round 9
// speedup vs baseline: 2.6749x; 2.0668x over previous
#include <cuda_runtime.h>
#include <cuda_bf16.h>
#include <cstdint>

#define BB   4
#define TT   4096
#define NINN 256
#define DD   64

// bf16 hi/lo split operands produced by the projection kernel (all row-major [B*T][64]).
__device__ unsigned short g_Qh[BB * TT * DD];
__device__ unsigned short g_Ql[BB * TT * DD];
__device__ unsigned short g_Kh[BB * TT * DD];
__device__ unsigned short g_Kl[BB * TT * DD];
__device__ unsigned short g_Vh[BB * TT * DD];
__device__ unsigned short g_Vl[BB * TT * DD];

// ---------------------------------------------------------------------------
// helpers
// ---------------------------------------------------------------------------
__device__ __forceinline__ uint32_t smem_u32(const void* p) {
    uint32_t a;
    asm("{ .reg .u64 t; cvta.to.shared.u64 t, %1; cvt.u32.u64 %0, t; }" : "=r"(a) : "l"(p));
    return a;
}

// pack two fp32 into bf16x2: low half <- lo, high half <- hi
__device__ __forceinline__ uint32_t bf2(float lo, float hi) {
    uint32_t r;
    asm("cvt.rn.bf16x2.f32 %0, %1, %2;" : "=r"(r) : "f"(hi), "f"(lo));
    return r;
}
// hi/lo split of a pair: h = RN_bf16(x),RN_bf16(y); l = residuals as bf16x2
__device__ __forceinline__ void split_pair(float x, float y, uint32_t& h, uint32_t& l) {
    h = bf2(x, y);
    const float xh = __uint_as_float(h << 16);
    const float yh = __uint_as_float(h & 0xffff0000u);
    l = bf2(x - xh, y - yh);
}

#define CP16(dst, src) \
    asm volatile("cp.async.cg.shared.global [%0], [%1], 16;" :: "r"(dst), "l"(src))
#define CP_COMMIT() asm volatile("cp.async.commit_group;" ::: "memory")
#define CP_WAIT0()  asm volatile("cp.async.wait_group 0;" ::: "memory")

__device__ __forceinline__ void ldm4(uint32_t r[4], uint32_t a) {
    asm volatile("ldmatrix.sync.aligned.m8n8.x4.shared.b16 {%0,%1,%2,%3}, [%4];"
        : "=r"(r[0]), "=r"(r[1]), "=r"(r[2]), "=r"(r[3]) : "r"(a));
}
__device__ __forceinline__ void ldm4t(uint32_t r[4], uint32_t a) {
    asm volatile("ldmatrix.sync.aligned.m8n8.x4.trans.shared.b16 {%0,%1,%2,%3}, [%4];"
        : "=r"(r[0]), "=r"(r[1]), "=r"(r[2]), "=r"(r[3]) : "r"(a));
}
__device__ __forceinline__ void mma_bf16(float c[4], const uint32_t a[4],
                                         uint32_t b0, uint32_t b1) {
    asm("mma.sync.aligned.m16n8k16.row.col.f32.bf16.bf16.f32 "
        "{%0,%1,%2,%3}, {%4,%5,%6,%7}, {%8,%9}, {%0,%1,%2,%3};"
        : "+f"(c[0]), "+f"(c[1]), "+f"(c[2]), "+f"(c[3])
        : "r"(a[0]), "r"(a[1]), "r"(a[2]), "r"(a[3]), "r"(b0), "r"(b1));
}

// swizzled byte offset inside a [rows][64 bf16] tile (128B rows, SW128)
__device__ __forceinline__ uint32_t swoff(int row, int chunk) {
    const uint32_t b = (uint32_t)(row * 128 + chunk * 16);
    return b ^ (((uint32_t)(row & 7)) << 4);
}

// ---------------------------------------------------------------------------
// Kernel 1: QKV projection -> bf16 hi/lo (row-major).  grid=(256,3), block=256.
// ---------------------------------------------------------------------------
__global__ __launch_bounds__(256) void qkv_kernel(
    const float* __restrict__ y,
    const float* __restrict__ Wq,
    const float* __restrict__ Wk,
    const float* __restrict__ Wv)
{
    __shared__ float sy[64 * 68];
    __shared__ float sw[64 * 64];

    const float* W;
    unsigned short *Oh, *Ol;
    if (blockIdx.y == 0)      { W = Wq; Oh = g_Qh; Ol = g_Ql; }
    else if (blockIdx.y == 1) { W = Wk; Oh = g_Kh; Ol = g_Kl; }
    else                      { W = Wv; Oh = g_Vh; Ol = g_Vl; }

    const int row0 = blockIdx.x * 64;
    const int tid  = threadIdx.x;
    const int tx   = tid & 15;
    const int ty   = tid >> 4;

    float acc[4][4];
#pragma unroll
    for (int i = 0; i < 4; i++)
#pragma unroll
        for (int j = 0; j < 4; j++) acc[i][j] = 0.f;

    for (int kt = 0; kt < NINN; kt += 64) {
        for (int i = tid; i < 1024; i += 256) {
            const int r = i >> 4, g = i & 15;
            *(float4*)&sy[r * 68 + g * 4] =
                *(const float4*)&y[(size_t)(row0 + r) * NINN + kt + g * 4];
            *(float4*)&sw[r * 64 + g * 4] =
                *(const float4*)&W[(size_t)(kt + r) * DD + g * 4];
        }
        __syncthreads();
#pragma unroll 8
        for (int k = 0; k < 64; k++) {
            const float a0 = sy[(ty * 4 + 0) * 68 + k];
            const float a1 = sy[(ty * 4 + 1) * 68 + k];
            const float a2 = sy[(ty * 4 + 2) * 68 + k];
            const float a3 = sy[(ty * 4 + 3) * 68 + k];
            const float4 b4 = *(const float4*)&sw[k * 64 + tx * 4];
            acc[0][0] += a0 * b4.x; acc[0][1] += a0 * b4.y; acc[0][2] += a0 * b4.z; acc[0][3] += a0 * b4.w;
            acc[1][0] += a1 * b4.x; acc[1][1] += a1 * b4.y; acc[1][2] += a1 * b4.z; acc[1][3] += a1 * b4.w;
            acc[2][0] += a2 * b4.x; acc[2][1] += a2 * b4.y; acc[2][2] += a2 * b4.z; acc[2][3] += a2 * b4.w;
            acc[3][0] += a3 * b4.x; acc[3][1] += a3 * b4.y; acc[3][2] += a3 * b4.z; acc[3][3] += a3 * b4.w;
        }
        __syncthreads();
    }

#pragma unroll
    for (int i = 0; i < 4; i++) {
        const int row = row0 + ty * 4 + i;
        uint32_t h01, l01, h23, l23;
        split_pair(acc[i][0], acc[i][1], h01, l01);
        split_pair(acc[i][2], acc[i][3], h23, l23);
        *(uint2*)&Oh[(size_t)row * DD + tx * 4] = make_uint2(h01, h23);
        *(uint2*)&Ol[(size_t)row * DD + tx * 4] = make_uint2(l01, l23);
    }
}

// ---------------------------------------------------------------------------
// Kernel 2: mma.sync bf16x3 causal flash attention.
// grid=128 (4 batches x 32 q-tiles of 128), block=256 (8 warps x 16 q-rows).
// SMEM (bytes): Qh 16K | Ql 16K | 2 x {Kh 8K | Kl 8K | Vh 8K | Vl 8K} = 96K.
// ---------------------------------------------------------------------------
#define SM_QH 0
#define SM_QL 16384
#define SM_KV 32768          /* + buf*32768; arr order Kh,Kl,Vh,Vl (8K each) */
#define SM_TOTAL 98304

__device__ __forceinline__ void load_kv(uint32_t SB, int buf, int b, int kbase, int tid) {
    const size_t off = (size_t)(b * TT + kbase) * DD;
    const char* srcs[4] = { (const char*)(g_Kh + off), (const char*)(g_Kl + off),
                            (const char*)(g_Vh + off), (const char*)(g_Vl + off) };
    const uint32_t base = SB + SM_KV + buf * 32768;
#pragma unroll
    for (int arr = 0; arr < 4; arr++)
#pragma unroll
        for (int u = 0; u < 2; u++) {
            const int i = tid + u * 256;           // 512 chunks per 8K array
            const int r = i >> 3, g = i & 7;
            CP16(base + arr * 8192 + swoff(r, g), srcs[arr] + r * 128 + g * 16);
        }
}

__global__ __launch_bounds__(256) void attn_kernel(float* __restrict__ out)
{
    extern __shared__ char smem[];
    const uint32_t SB = smem_u32(smem);

    const int tid  = threadIdx.x;
    const int lane = tid & 31;
    const int w    = tid >> 5;
    const int b    = blockIdx.x & 3;
    const int qt   = 31 - (blockIdx.x >> 2);   // heavy q-tiles first
    const int q0   = qt * 128;
    const int nt   = 2 * qt + 2;

    const int lrow   = lane & 15;
    const int lchunk = lane >> 4;
    const int rlo_g  = q0 + w * 16 + (lane >> 2);
    const int rhi_g  = rlo_g + 8;

    // ---- initial loads: Q hi/lo + K/V buf0 ----
    {
        const size_t off = (size_t)(b * TT + q0) * DD;
        const char* qh = (const char*)(g_Qh + off);
        const char* ql = (const char*)(g_Ql + off);
#pragma unroll
        for (int u = 0; u < 4; u++) {             // 1024 chunks per 16K array
            const int i = tid + u * 256;
            const int r = i >> 3, g = i & 7;
            CP16(SB + SM_QH + swoff(r, g), qh + r * 128 + g * 16);
            CP16(SB + SM_QL + swoff(r, g), ql + r * 128 + g * 16);
        }
        load_kv(SB, 0, b, 0, tid);
        CP_COMMIT();
        CP_WAIT0();
        __syncthreads();
    }

    // ---- Q fragments (held in registers for the whole kernel) ----
    uint32_t Ah[4][4], Al[4][4];
#pragma unroll
    for (int kc = 0; kc < 4; kc++) {
        ldm4(Ah[kc], SB + SM_QH + swoff(w * 16 + lrow, 2 * kc + lchunk));
        ldm4(Al[kc], SB + SM_QL + swoff(w * 16 + lrow, 2 * kc + lchunk));
    }

    float O[8][4];
#pragma unroll
    for (int n = 0; n < 8; n++)
#pragma unroll
        for (int e = 0; e < 4; e++) O[n][e] = 0.f;
    float m_lo = -1e30f, m_hi = -1e30f, l_lo = 0.f, l_hi = 0.f;

    for (int t = 0; t < nt; t++) {
        const int buf = t & 1;
        const uint32_t KB = SB + SM_KV + buf * 32768;
        if (t + 1 < nt) { load_kv(SB, buf ^ 1, b, (t + 1) * 64, tid); CP_COMMIT(); }

        // ---- S = Qh Kh^T + Qh Kl^T + Ql Kh^T ----
        float S[8][4];
#pragma unroll
        for (int n = 0; n < 8; n++)
#pragma unroll
            for (int e = 0; e < 4; e++) S[n][e] = 0.f;

#pragma unroll
        for (int kc = 0; kc < 4; kc++) {
            uint32_t kh[4][4], kl[4][4];
#pragma unroll
            for (int jt = 0; jt < 4; jt++)
                ldm4(kh[jt], KB + swoff(jt * 16 + lrow, 2 * kc + lchunk));
#pragma unroll
            for (int jt = 0; jt < 4; jt++) {
                mma_bf16(S[2 * jt],     Ah[kc], kh[jt][0], kh[jt][2]);
                mma_bf16(S[2 * jt + 1], Ah[kc], kh[jt][1], kh[jt][3]);
            }
#pragma unroll
            for (int jt = 0; jt < 4; jt++) {
                mma_bf16(S[2 * jt],     Al[kc], kh[jt][0], kh[jt][2]);
                mma_bf16(S[2 * jt + 1], Al[kc], kh[jt][1], kh[jt][3]);
            }
#pragma unroll
            for (int jt = 0; jt < 4; jt++)
                ldm4(kl[jt], KB + 8192 + swoff(jt * 16 + lrow, 2 * kc + lchunk));
#pragma unroll
            for (int jt = 0; jt < 4; jt++) {
                mma_bf16(S[2 * jt],     Ah[kc], kl[jt][0], kl[jt][2]);
                mma_bf16(S[2 * jt + 1], Ah[kc], kl[jt][1], kl[jt][3]);
            }
        }

        // ---- online softmax (in registers) ----
        const int kbase = t * 64;
        const bool tmask = (kbase + 63 > q0 + w * 16);
        float mx_lo = -1e30f, mx_hi = -1e30f;
#pragma unroll
        for (int n = 0; n < 8; n++) {
#pragma unroll
            for (int e = 0; e < 4; e++) {
                float v = S[n][e] * 0.125f;       // 1/sqrt(64)
                if (tmask) {
                    const int j = kbase + n * 8 + (lane & 3) * 2 + (e & 1);
                    const int r = (e < 2) ? rlo_g : rhi_g;
                    if (j > r) v = -1e30f;
                }
                S[n][e] = v;
            }
            mx_lo = fmaxf(mx_lo, fmaxf(S[n][0], S[n][1]));
            mx_hi = fmaxf(mx_hi, fmaxf(S[n][2], S[n][3]));
        }
        mx_lo = fmaxf(mx_lo, __shfl_xor_sync(0xffffffffu, mx_lo, 1));
        mx_lo = fmaxf(mx_lo, __shfl_xor_sync(0xffffffffu, mx_lo, 2));
        mx_hi = fmaxf(mx_hi, __shfl_xor_sync(0xffffffffu, mx_hi, 1));
        mx_hi = fmaxf(mx_hi, __shfl_xor_sync(0xffffffffu, mx_hi, 2));

        const float mn_lo = fmaxf(m_lo, mx_lo);
        const float mn_hi = fmaxf(m_hi, mx_hi);
        const float corr_lo = __expf(m_lo - mn_lo);
        const float corr_hi = __expf(m_hi - mn_hi);
        m_lo = mn_lo; m_hi = mn_hi;

        float ls_lo = 0.f, ls_hi = 0.f;
#pragma unroll
        for (int n = 0; n < 8; n++) {
            S[n][0] = __expf(S[n][0] - mn_lo);
            S[n][1] = __expf(S[n][1] - mn_lo);
            S[n][2] = __expf(S[n][2] - mn_hi);
            S[n][3] = __expf(S[n][3] - mn_hi);
            ls_lo += S[n][0] + S[n][1];
            ls_hi += S[n][2] + S[n][3];
        }
        ls_lo += __shfl_xor_sync(0xffffffffu, ls_lo, 1);
        ls_lo += __shfl_xor_sync(0xffffffffu, ls_lo, 2);
        ls_hi += __shfl_xor_sync(0xffffffffu, ls_hi, 1);
        ls_hi += __shfl_xor_sync(0xffffffffu, ls_hi, 2);
        l_lo = l_lo * corr_lo + ls_lo;
        l_hi = l_hi * corr_hi + ls_hi;

#pragma unroll
        for (int n = 0; n < 8; n++) {
            O[n][0] *= corr_lo; O[n][1] *= corr_lo;
            O[n][2] *= corr_hi; O[n][3] *= corr_hi;
        }

        // ---- P hi/lo A-fragments straight from S registers ----
        uint32_t ph[4][4], pl[4][4];
#pragma unroll
        for (int kc = 0; kc < 4; kc++) {
            split_pair(S[2 * kc][0],     S[2 * kc][1],     ph[kc][0], pl[kc][0]);
            split_pair(S[2 * kc][2],     S[2 * kc][3],     ph[kc][1], pl[kc][1]);
            split_pair(S[2 * kc + 1][0], S[2 * kc + 1][1], ph[kc][2], pl[kc][2]);
            split_pair(S[2 * kc + 1][2], S[2 * kc + 1][3], ph[kc][3], pl[kc][3]);
        }

        // ---- O += Ph Vh + Pl Vh + Ph Vl ----
        const uint32_t VB = KB + 16384;
#pragma unroll
        for (int kc = 0; kc < 4; kc++) {
            uint32_t vh[4][4], vl[4][4];
#pragma unroll
            for (int dt = 0; dt < 4; dt++)
                ldm4t(vh[dt], VB + swoff(kc * 16 + lrow, 2 * dt + lchunk));
#pragma unroll
            for (int dt = 0; dt < 4; dt++) {
                mma_bf16(O[2 * dt],     ph[kc], vh[dt][0], vh[dt][1]);
                mma_bf16(O[2 * dt + 1], ph[kc], vh[dt][2], vh[dt][3]);
            }
#pragma unroll
            for (int dt = 0; dt < 4; dt++) {
                mma_bf16(O[2 * dt],     pl[kc], vh[dt][0], vh[dt][1]);
                mma_bf16(O[2 * dt + 1], pl[kc], vh[dt][2], vh[dt][3]);
            }
#pragma unroll
            for (int dt = 0; dt < 4; dt++)
                ldm4t(vl[dt], VB + 8192 + swoff(kc * 16 + lrow, 2 * dt + lchunk));
#pragma unroll
            for (int dt = 0; dt < 4; dt++) {
                mma_bf16(O[2 * dt],     ph[kc], vl[dt][0], vl[dt][1]);
                mma_bf16(O[2 * dt + 1], ph[kc], vl[dt][2], vl[dt][3]);
            }
        }

        CP_WAIT0();
        __syncthreads();
    }

    // ---- epilogue ----
    const float il_lo = 1.f / l_lo;
    const float il_hi = 1.f / l_hi;
    float* orow_lo = out + (size_t)(b * TT + rlo_g) * DD + (lane & 3) * 2;
    float* orow_hi = out + (size_t)(b * TT + rhi_g) * DD + (lane & 3) * 2;
#pragma unroll
    for (int n = 0; n < 8; n++) {
        float2 v0, v1;
        v0.x = O[n][0] * il_lo; v0.y = O[n][1] * il_lo;
        v1.x = O[n][2] * il_hi; v1.y = O[n][3] * il_hi;
        *(float2*)(orow_lo + n * 8) = v0;
        *(float2*)(orow_hi + n * 8) = v1;
    }
}

// ---------------------------------------------------------------------------
extern "C" void kernel_launch(void* const* d_in, const int* in_sizes, int n_in,
                              void* d_out, int out_size)
{
    (void)in_sizes; (void)n_in; (void)out_size;
    const float* y  = (const float*)d_in[0];
    const float* Wq = (const float*)d_in[1];
    const float* Wk = (const float*)d_in[2];
    const float* Wv = (const float*)d_in[3];

    qkv_kernel<<<dim3((BB * TT) / 64, 3), 256>>>(y, Wq, Wk, Wv);

    cudaFuncSetAttribute(attn_kernel,
                         cudaFuncAttributeMaxDynamicSharedMemorySize, SM_TOTAL);
    attn_kernel<<<BB * (TT / 128), 256, SM_TOTAL>>>((float*)d_out);
}

// round 10
// speedup vs baseline: 3.9184x; 1.4648x over previous
#include <cuda_runtime.h>
#include <cuda_bf16.h>
#include <cstdint>

#define BB   4
#define TT   4096
#define NINN 256
#define DD   64

// bf16 hi/lo split operands produced by the projection kernel (all row-major [B*T][64]).
__device__ unsigned short g_Qh[BB * TT * DD];
__device__ unsigned short g_Ql[BB * TT * DD];
__device__ unsigned short g_Kh[BB * TT * DD];
__device__ unsigned short g_Kl[BB * TT * DD];
__device__ unsigned short g_Vh[BB * TT * DD];
__device__ unsigned short g_Vl[BB * TT * DD];

// Split-K partial scratch: [role][b][pair][row 0..127][d 0..63]  (4 MB) + m/l.
__device__ float g_Op[2][BB][16][128][64];
__device__ float g_Om[2][BB][16][128];
__device__ float g_Ol[2][BB][16][128];

// log2(e)/sqrt(64): scores scaled straight into the exp2 domain.
#define SCALE2 0.1803368801111204f

// ---------------------------------------------------------------------------
// helpers
// ---------------------------------------------------------------------------
__device__ __forceinline__ uint32_t smem_u32(const void* p) {
    uint32_t a;
    asm("{ .reg .u64 t; cvta.to.shared.u64 t, %1; cvt.u32.u64 %0, t; }" : "=r"(a) : "l"(p));
    return a;
}
__device__ __forceinline__ float ex2(float x) {
    float r;
    asm("ex2.approx.ftz.f32 %0, %1;" : "=f"(r) : "f"(x));
    return r;
}

// pack two fp32 into bf16x2: low half <- lo, high half <- hi
__device__ __forceinline__ uint32_t bf2(float lo, float hi) {
    uint32_t r;
    asm("cvt.rn.bf16x2.f32 %0, %1, %2;" : "=r"(r) : "f"(hi), "f"(lo));
    return r;
}
// hi/lo split of a pair: h = RN_bf16(x),RN_bf16(y); l = residuals as bf16x2
__device__ __forceinline__ void split_pair(float x, float y, uint32_t& h, uint32_t& l) {
    h = bf2(x, y);
    const float xh = __uint_as_float(h << 16);
    const float yh = __uint_as_float(h & 0xffff0000u);
    l = bf2(x - xh, y - yh);
}

#define CP16(dst, src) \
    asm volatile("cp.async.cg.shared.global [%0], [%1], 16;" :: "r"(dst), "l"(src))
#define CP_COMMIT() asm volatile("cp.async.commit_group;" ::: "memory")
#define CP_WAIT0()  asm volatile("cp.async.wait_group 0;" ::: "memory")

__device__ __forceinline__ void ldm4(uint32_t r[4], uint32_t a) {
    asm volatile("ldmatrix.sync.aligned.m8n8.x4.shared.b16 {%0,%1,%2,%3}, [%4];"
        : "=r"(r[0]), "=r"(r[1]), "=r"(r[2]), "=r"(r[3]) : "r"(a));
}
__device__ __forceinline__ void ldm4t(uint32_t r[4], uint32_t a) {
    asm volatile("ldmatrix.sync.aligned.m8n8.x4.trans.shared.b16 {%0,%1,%2,%3}, [%4];"
        : "=r"(r[0]), "=r"(r[1]), "=r"(r[2]), "=r"(r[3]) : "r"(a));
}
__device__ __forceinline__ void mma_bf16(float c[4], const uint32_t a[4],
                                         uint32_t b0, uint32_t b1) {
    asm("mma.sync.aligned.m16n8k16.row.col.f32.bf16.bf16.f32 "
        "{%0,%1,%2,%3}, {%4,%5,%6,%7}, {%8,%9}, {%0,%1,%2,%3};"
        : "+f"(c[0]), "+f"(c[1]), "+f"(c[2]), "+f"(c[3])
        : "r"(a[0]), "r"(a[1]), "r"(a[2]), "r"(a[3]), "r"(b0), "r"(b1));
}

// swizzled byte offset inside a [rows][64 bf16] tile (128B rows, SW128)
__device__ __forceinline__ uint32_t swoff(int row, int chunk) {
    const uint32_t b = (uint32_t)(row * 128 + chunk * 16);
    return b ^ (((uint32_t)(row & 7)) << 4);
}

// ---------------------------------------------------------------------------
// Kernel 1: QKV projection -> bf16 hi/lo (row-major).  grid=(256,3), block=256.
// ---------------------------------------------------------------------------
__global__ __launch_bounds__(256) void qkv_kernel(
    const float* __restrict__ y,
    const float* __restrict__ Wq,
    const float* __restrict__ Wk,
    const float* __restrict__ Wv)
{
    __shared__ float sy[64 * 68];
    __shared__ float sw[64 * 64];

    const float* W;
    unsigned short *Oh, *Ol;
    if (blockIdx.y == 0)      { W = Wq; Oh = g_Qh; Ol = g_Ql; }
    else if (blockIdx.y == 1) { W = Wk; Oh = g_Kh; Ol = g_Kl; }
    else                      { W = Wv; Oh = g_Vh; Ol = g_Vl; }

    const int row0 = blockIdx.x * 64;
    const int tid  = threadIdx.x;
    const int tx   = tid & 15;
    const int ty   = tid >> 4;

    float acc[4][4];
#pragma unroll
    for (int i = 0; i < 4; i++)
#pragma unroll
        for (int j = 0; j < 4; j++) acc[i][j] = 0.f;

    for (int kt = 0; kt < NINN; kt += 64) {
        for (int i = tid; i < 1024; i += 256) {
            const int r = i >> 4, g = i & 15;
            *(float4*)&sy[r * 68 + g * 4] =
                *(const float4*)&y[(size_t)(row0 + r) * NINN + kt + g * 4];
            *(float4*)&sw[r * 64 + g * 4] =
                *(const float4*)&W[(size_t)(kt + r) * DD + g * 4];
        }
        __syncthreads();
#pragma unroll 8
        for (int k = 0; k < 64; k++) {
            const float a0 = sy[(ty * 4 + 0) * 68 + k];
            const float a1 = sy[(ty * 4 + 1) * 68 + k];
            const float a2 = sy[(ty * 4 + 2) * 68 + k];
            const float a3 = sy[(ty * 4 + 3) * 68 + k];
            const float4 b4 = *(const float4*)&sw[k * 64 + tx * 4];
            acc[0][0] += a0 * b4.x; acc[0][1] += a0 * b4.y; acc[0][2] += a0 * b4.z; acc[0][3] += a0 * b4.w;
            acc[1][0] += a1 * b4.x; acc[1][1] += a1 * b4.y; acc[1][2] += a1 * b4.z; acc[1][3] += a1 * b4.w;
            acc[2][0] += a2 * b4.x; acc[2][1] += a2 * b4.y; acc[2][2] += a2 * b4.z; acc[2][3] += a2 * b4.w;
            acc[3][0] += a3 * b4.x; acc[3][1] += a3 * b4.y; acc[3][2] += a3 * b4.z; acc[3][3] += a3 * b4.w;
        }
        __syncthreads();
    }

#pragma unroll
    for (int i = 0; i < 4; i++) {
        const int row = row0 + ty * 4 + i;
        uint32_t h01, l01, h23, l23;
        split_pair(acc[i][0], acc[i][1], h01, l01);
        split_pair(acc[i][2], acc[i][3], h23, l23);
        *(uint2*)&Oh[(size_t)row * DD + tx * 4] = make_uint2(h01, h23);
        *(uint2*)&Ol[(size_t)row * DD + tx * 4] = make_uint2(l01, l23);
    }
}

// ---------------------------------------------------------------------------
// Kernel 2: mma.sync bf16x3 causal flash attention, balanced split-K pairs.
// grid = 128: blockIdx -> (b = &3, pair = (>>2)>>1, role = (>>2)&1).
//   role 0: q-tile (31-pair), k-tiles [0,33)            -> partial 0
//   role 1: q-tile (pair) full -> direct; q-tile (31-pair), k-tiles [33, 64-2p) -> partial 1
// Every CTA does exactly 33 k-tile units.
// SMEM: Qh 16K | Ql 16K | 2 x {Kh 8K | Kl 8K | Vh 8K | Vl 8K} = 96K.
// ---------------------------------------------------------------------------
#define SM_QH 0
#define SM_QL 16384
#define SM_KV 32768
#define SM_TOTAL 98304

__device__ __forceinline__ void load_kv(uint32_t SB, int buf, int b, int kbase, int tid) {
    const size_t off = (size_t)(b * TT + kbase) * DD;
    const char* srcs[4] = { (const char*)(g_Kh + off), (const char*)(g_Kl + off),
                            (const char*)(g_Vh + off), (const char*)(g_Vl + off) };
    const uint32_t base = SB + SM_KV + buf * 32768;
#pragma unroll
    for (int arr = 0; arr < 4; arr++)
#pragma unroll
        for (int u = 0; u < 2; u++) {
            const int i = tid + u * 256;
            const int r = i >> 3, g = i & 7;
            CP16(base + arr * 8192 + swoff(r, g), srcs[arr] + r * 128 + g * 16);
        }
}

__device__ __forceinline__ void run_segment(
    uint32_t SB, float* __restrict__ out,
    int b, int pairi, int qtile, int t0, int t1, int partIdx)
{
    const int tid  = threadIdx.x;
    const int lane = tid & 31;
    const int w    = tid >> 5;
    const int q0   = qtile * 128;

    const int lrow   = lane & 15;
    const int lchunk = lane >> 4;
    const int rlo    = w * 16 + (lane >> 2);   // row within tile
    const int rhi    = rlo + 8;
    const int rlo_g  = q0 + rlo;
    const int rhi_g  = q0 + rhi;

    // ---- prologue: Q hi/lo + first K/V buffer ----
    {
        const size_t off = (size_t)(b * TT + q0) * DD;
        const char* qh = (const char*)(g_Qh + off);
        const char* ql = (const char*)(g_Ql + off);
#pragma unroll
        for (int u = 0; u < 4; u++) {
            const int i = tid + u * 256;
            const int r = i >> 3, g = i & 7;
            CP16(SB + SM_QH + swoff(r, g), qh + r * 128 + g * 16);
            CP16(SB + SM_QL + swoff(r, g), ql + r * 128 + g * 16);
        }
        load_kv(SB, 0, b, t0 * 64, tid);
        CP_COMMIT();
        CP_WAIT0();
        __syncthreads();
    }

    uint32_t Ah[4][4], Al[4][4];
#pragma unroll
    for (int kc = 0; kc < 4; kc++) {
        ldm4(Ah[kc], SB + SM_QH + swoff(w * 16 + lrow, 2 * kc + lchunk));
        ldm4(Al[kc], SB + SM_QL + swoff(w * 16 + lrow, 2 * kc + lchunk));
    }

    float O[8][4];
#pragma unroll
    for (int n = 0; n < 8; n++)
#pragma unroll
        for (int e = 0; e < 4; e++) O[n][e] = 0.f;
    float m_lo = -1e30f, m_hi = -1e30f, l_lo = 0.f, l_hi = 0.f;

    for (int t = t0; t < t1; t++) {
        const int buf = (t - t0) & 1;
        const uint32_t KB = SB + SM_KV + buf * 32768;
        if (t + 1 < t1) { load_kv(SB, buf ^ 1, b, (t + 1) * 64, tid); CP_COMMIT(); }

        // ---- S = Qh Kh^T + Ql Kh^T + Qh Kl^T ----
        float S[8][4];
#pragma unroll
        for (int n = 0; n < 8; n++)
#pragma unroll
            for (int e = 0; e < 4; e++) S[n][e] = 0.f;

#pragma unroll
        for (int kc = 0; kc < 4; kc++) {
            uint32_t kh[4][4], kl[4][4];
#pragma unroll
            for (int jt = 0; jt < 4; jt++)
                ldm4(kh[jt], KB + swoff(jt * 16 + lrow, 2 * kc + lchunk));
#pragma unroll
            for (int jt = 0; jt < 4; jt++) {
                mma_bf16(S[2 * jt],     Ah[kc], kh[jt][0], kh[jt][2]);
                mma_bf16(S[2 * jt + 1], Ah[kc], kh[jt][1], kh[jt][3]);
            }
#pragma unroll
            for (int jt = 0; jt < 4; jt++) {
                mma_bf16(S[2 * jt],     Al[kc], kh[jt][0], kh[jt][2]);
                mma_bf16(S[2 * jt + 1], Al[kc], kh[jt][1], kh[jt][3]);
            }
#pragma unroll
            for (int jt = 0; jt < 4; jt++)
                ldm4(kl[jt], KB + 8192 + swoff(jt * 16 + lrow, 2 * kc + lchunk));
#pragma unroll
            for (int jt = 0; jt < 4; jt++) {
                mma_bf16(S[2 * jt],     Ah[kc], kl[jt][0], kl[jt][2]);
                mma_bf16(S[2 * jt + 1], Ah[kc], kl[jt][1], kl[jt][3]);
            }
        }

        // ---- online softmax in the exp2 domain ----
        const int kbase = t * 64;
        const bool tmask = (kbase + 63 > q0 + w * 16);
        float mx_lo = -1e30f, mx_hi = -1e30f;
#pragma unroll
        for (int n = 0; n < 8; n++) {
#pragma unroll
            for (int e = 0; e < 4; e++) {
                float v = S[n][e] * SCALE2;
                if (tmask) {
                    const int j = kbase + n * 8 + (lane & 3) * 2 + (e & 1);
                    const int r = (e < 2) ? rlo_g : rhi_g;
                    if (j > r) v = -1e30f;
                }
                S[n][e] = v;
            }
            mx_lo = fmaxf(mx_lo, fmaxf(S[n][0], S[n][1]));
            mx_hi = fmaxf(mx_hi, fmaxf(S[n][2], S[n][3]));
        }
        mx_lo = fmaxf(mx_lo, __shfl_xor_sync(0xffffffffu, mx_lo, 1));
        mx_lo = fmaxf(mx_lo, __shfl_xor_sync(0xffffffffu, mx_lo, 2));
        mx_hi = fmaxf(mx_hi, __shfl_xor_sync(0xffffffffu, mx_hi, 1));
        mx_hi = fmaxf(mx_hi, __shfl_xor_sync(0xffffffffu, mx_hi, 2));

        const float mn_lo = fmaxf(m_lo, mx_lo);
        const float mn_hi = fmaxf(m_hi, mx_hi);
        const float corr_lo = ex2(m_lo - mn_lo);
        const float corr_hi = ex2(m_hi - mn_hi);
        m_lo = mn_lo; m_hi = mn_hi;

        float ls_lo = 0.f, ls_hi = 0.f;
#pragma unroll
        for (int n = 0; n < 8; n++) {
            S[n][0] = ex2(S[n][0] - mn_lo);
            S[n][1] = ex2(S[n][1] - mn_lo);
            S[n][2] = ex2(S[n][2] - mn_hi);
            S[n][3] = ex2(S[n][3] - mn_hi);
            ls_lo += S[n][0] + S[n][1];
            ls_hi += S[n][2] + S[n][3];
        }
        ls_lo += __shfl_xor_sync(0xffffffffu, ls_lo, 1);
        ls_lo += __shfl_xor_sync(0xffffffffu, ls_lo, 2);
        ls_hi += __shfl_xor_sync(0xffffffffu, ls_hi, 1);
        ls_hi += __shfl_xor_sync(0xffffffffu, ls_hi, 2);
        l_lo = l_lo * corr_lo + ls_lo;
        l_hi = l_hi * corr_hi + ls_hi;

#pragma unroll
        for (int n = 0; n < 8; n++) {
            O[n][0] *= corr_lo; O[n][1] *= corr_lo;
            O[n][2] *= corr_hi; O[n][3] *= corr_hi;
        }

        // ---- P hi/lo A-fragments straight from S registers ----
        uint32_t ph[4][4], pl[4][4];
#pragma unroll
        for (int kc = 0; kc < 4; kc++) {
            split_pair(S[2 * kc][0],     S[2 * kc][1],     ph[kc][0], pl[kc][0]);
            split_pair(S[2 * kc][2],     S[2 * kc][3],     ph[kc][1], pl[kc][1]);
            split_pair(S[2 * kc + 1][0], S[2 * kc + 1][1], ph[kc][2], pl[kc][2]);
            split_pair(S[2 * kc + 1][2], S[2 * kc + 1][3], ph[kc][3], pl[kc][3]);
        }

        // ---- O += Ph Vh + Pl Vh + Ph Vl ----
        const uint32_t VB = KB + 16384;
#pragma unroll
        for (int kc = 0; kc < 4; kc++) {
            uint32_t vh[4][4], vl[4][4];
#pragma unroll
            for (int dt = 0; dt < 4; dt++)
                ldm4t(vh[dt], VB + swoff(kc * 16 + lrow, 2 * dt + lchunk));
#pragma unroll
            for (int dt = 0; dt < 4; dt++) {
                mma_bf16(O[2 * dt],     ph[kc], vh[dt][0], vh[dt][1]);
                mma_bf16(O[2 * dt + 1], ph[kc], vh[dt][2], vh[dt][3]);
            }
#pragma unroll
            for (int dt = 0; dt < 4; dt++) {
                mma_bf16(O[2 * dt],     pl[kc], vh[dt][0], vh[dt][1]);
                mma_bf16(O[2 * dt + 1], pl[kc], vh[dt][2], vh[dt][3]);
            }
#pragma unroll
            for (int dt = 0; dt < 4; dt++)
                ldm4t(vl[dt], VB + 8192 + swoff(kc * 16 + lrow, 2 * dt + lchunk));
#pragma unroll
            for (int dt = 0; dt < 4; dt++) {
                mma_bf16(O[2 * dt],     ph[kc], vl[dt][0], vl[dt][1]);
                mma_bf16(O[2 * dt + 1], ph[kc], vl[dt][2], vl[dt][3]);
            }
        }

        CP_WAIT0();
        __syncthreads();
    }

    // ---- segment epilogue ----
    if (partIdx < 0) {
        const float il_lo = 1.f / l_lo;
        const float il_hi = 1.f / l_hi;
        float* orow_lo = out + (size_t)(b * TT + rlo_g) * DD + (lane & 3) * 2;
        float* orow_hi = out + (size_t)(b * TT + rhi_g) * DD + (lane & 3) * 2;
#pragma unroll
        for (int n = 0; n < 8; n++) {
            float2 v0, v1;
            v0.x = O[n][0] * il_lo; v0.y = O[n][1] * il_lo;
            v1.x = O[n][2] * il_hi; v1.y = O[n][3] * il_hi;
            *(float2*)(orow_lo + n * 8) = v0;
            *(float2*)(orow_hi + n * 8) = v1;
        }
    } else {
        float* Op = &g_Op[partIdx][b][pairi][0][0];
        const int col = (lane & 3) * 2;
#pragma unroll
        for (int n = 0; n < 8; n++) {
            *(float2*)&Op[rlo * 64 + n * 8 + col] = make_float2(O[n][0], O[n][1]);
            *(float2*)&Op[rhi * 64 + n * 8 + col] = make_float2(O[n][2], O[n][3]);
        }
        if ((lane & 3) == 0) {
            g_Om[partIdx][b][pairi][rlo] = m_lo;
            g_Ol[partIdx][b][pairi][rlo] = l_lo;
            g_Om[partIdx][b][pairi][rhi] = m_hi;
            g_Ol[partIdx][b][pairi][rhi] = l_hi;
        }
    }
}

__global__ __launch_bounds__(256) void attn_kernel(float* __restrict__ out)
{
    extern __shared__ char smem[];
    const uint32_t SB = smem_u32(smem);

    const int bi    = blockIdx.x;
    const int b     = bi & 3;
    const int pi    = bi >> 2;        // 0..31
    const int pairi = pi >> 1;        // 0..15
    const int role  = pi & 1;

    const int qa = 31 - pairi;        // split q-tile
    if (role == 0) {
        run_segment(SB, out, b, pairi, qa, 0, 33, 0);
    } else {
        run_segment(SB, out, b, pairi, pairi, 0, 2 * pairi + 2, -1);
        run_segment(SB, out, b, pairi, qa, 33, 64 - 2 * pairi, 1);
    }
}

// ---------------------------------------------------------------------------
// Kernel 3: merge the two split-K partials per split q-tile.
// grid = 64 (b x pair), block = 128 (one row each).
// ---------------------------------------------------------------------------
__global__ __launch_bounds__(128) void merge_kernel(float* __restrict__ out)
{
    const int blk   = blockIdx.x;
    const int b     = blk & 3;
    const int pairi = blk >> 2;
    const int row   = threadIdx.x;
    const int qa    = 31 - pairi;

    const float m0 = g_Om[0][b][pairi][row];
    const float m1 = g_Om[1][b][pairi][row];
    const float l0 = g_Ol[0][b][pairi][row];
    const float l1 = g_Ol[1][b][pairi][row];
    const float mm = fmaxf(m0, m1);
    const float c0 = ex2(m0 - mm);
    const float c1 = ex2(m1 - mm);
    const float inv = 1.f / (l0 * c0 + l1 * c1);

    const float* O0 = &g_Op[0][b][pairi][row][0];
    const float* O1 = &g_Op[1][b][pairi][row][0];
    float* orow = out + ((size_t)(b * TT + qa * 128 + row)) * DD;
#pragma unroll
    for (int g = 0; g < 16; g++) {
        const float4 a = *(const float4*)&O0[g * 4];
        const float4 c = *(const float4*)&O1[g * 4];
        float4 v;
        v.x = (a.x * c0 + c.x * c1) * inv;
        v.y = (a.y * c0 + c.y * c1) * inv;
        v.z = (a.z * c0 + c.z * c1) * inv;
        v.w = (a.w * c0 + c.w * c1) * inv;
        *(float4*)&orow[g * 4] = v;
    }
}

// ---------------------------------------------------------------------------
extern "C" void kernel_launch(void* const* d_in, const int* in_sizes, int n_in,
                              void* d_out, int out_size)
{
    (void)in_sizes; (void)n_in; (void)out_size;
    const float* y  = (const float*)d_in[0];
    const float* Wq = (const float*)d_in[1];
    const float* Wk = (const float*)d_in[2];
    const float* Wv = (const float*)d_in[3];

    qkv_kernel<<<dim3((BB * TT) / 64, 3), 256>>>(y, Wq, Wk, Wv);

    cudaFuncSetAttribute(attn_kernel,
                         cudaFuncAttributeMaxDynamicSharedMemorySize, SM_TOTAL);
    attn_kernel<<<128, 256, SM_TOTAL>>>((float*)d_out);

    merge_kernel<<<64, 128>>>((float*)d_out);
}

// round 16
// speedup vs baseline: 4.9362x; 1.2598x over previous
#include <cuda_runtime.h>
#include <cuda_bf16.h>
#include <cstdint>

#define BB   4
#define TT   4096
#define NINN 256
#define DD   64

// bf16 hi/lo split operands (all row-major [B*T][64]).
__device__ unsigned short g_Qh[BB * TT * DD];
__device__ unsigned short g_Ql[BB * TT * DD];
__device__ unsigned short g_Kh[BB * TT * DD];
__device__ unsigned short g_Kl[BB * TT * DD];
__device__ unsigned short g_Vh[BB * TT * DD];
__device__ unsigned short g_Vl[BB * TT * DD];

// Pre-split weights: [mat][k 0..255][n 0..63] bf16 hi/lo.
__device__ unsigned short g_Wh[3 * NINN * DD];
__device__ unsigned short g_Wl[3 * NINN * DD];

// Split-K partial scratch: [role][b][pair][row 0..127][d 0..63] + m/l.
__device__ float g_Op[2][BB][16][128][64];
__device__ float g_Om[2][BB][16][128];
__device__ float g_Ol[2][BB][16][128];

// log2(e)/sqrt(64): scores scaled straight into the exp2 domain.
#define SCALE2 0.1803368801111204f

// ---------------------------------------------------------------------------
// helpers
// ---------------------------------------------------------------------------
__device__ __forceinline__ uint32_t smem_u32(const void* p) {
    uint32_t a;
    asm("{ .reg .u64 t; cvta.to.shared.u64 t, %1; cvt.u32.u64 %0, t; }" : "=r"(a) : "l"(p));
    return a;
}
__device__ __forceinline__ float ex2(float x) {
    float r;
    asm("ex2.approx.ftz.f32 %0, %1;" : "=f"(r) : "f"(x));
    return r;
}

// pack two fp32 into bf16x2: low half <- lo, high half <- hi
__device__ __forceinline__ uint32_t bf2(float lo, float hi) {
    uint32_t r;
    asm("cvt.rn.bf16x2.f32 %0, %1, %2;" : "=r"(r) : "f"(hi), "f"(lo));
    return r;
}
// hi/lo split of a pair: h = RN_bf16(x),RN_bf16(y); l = residuals as bf16x2
__device__ __forceinline__ void split_pair(float x, float y, uint32_t& h, uint32_t& l) {
    h = bf2(x, y);
    const float xh = __uint_as_float(h << 16);
    const float yh = __uint_as_float(h & 0xffff0000u);
    l = bf2(x - xh, y - yh);
}

#define CP16(dst, src) \
    asm volatile("cp.async.cg.shared.global [%0], [%1], 16;" :: "r"(dst), "l"(src))
#define CP_COMMIT() asm volatile("cp.async.commit_group;" ::: "memory")
#define CP_WAIT0()  asm volatile("cp.async.wait_group 0;" ::: "memory")

__device__ __forceinline__ void ldm4(uint32_t r[4], uint32_t a) {
    asm volatile("ldmatrix.sync.aligned.m8n8.x4.shared.b16 {%0,%1,%2,%3}, [%4];"
        : "=r"(r[0]), "=r"(r[1]), "=r"(r[2]), "=r"(r[3]) : "r"(a));
}
__device__ __forceinline__ void ldm4t(uint32_t r[4], uint32_t a) {
    asm volatile("ldmatrix.sync.aligned.m8n8.x4.trans.shared.b16 {%0,%1,%2,%3}, [%4];"
        : "=r"(r[0]), "=r"(r[1]), "=r"(r[2]), "=r"(r[3]) : "r"(a));
}
__device__ __forceinline__ void mma_bf16(float c[4], const uint32_t a[4],
                                         uint32_t b0, uint32_t b1) {
    asm("mma.sync.aligned.m16n8k16.row.col.f32.bf16.bf16.f32 "
        "{%0,%1,%2,%3}, {%4,%5,%6,%7}, {%8,%9}, {%0,%1,%2,%3};"
        : "+f"(c[0]), "+f"(c[1]), "+f"(c[2]), "+f"(c[3])
        : "r"(a[0]), "r"(a[1]), "r"(a[2]), "r"(a[3]), "r"(b0), "r"(b1));
}

// swizzled byte offset inside a [rows][64 bf16] tile (128B rows, SW128)
__device__ __forceinline__ uint32_t swoff(int row, int chunk) {
    const uint32_t b = (uint32_t)(row * 128 + chunk * 16);
    return b ^ (((uint32_t)(row & 7)) << 4);
}

// ---------------------------------------------------------------------------
// Kernel 0: split W (fp32) -> bf16 hi/lo.  3*256*64 = 49152 elements.
// ---------------------------------------------------------------------------
__global__ __launch_bounds__(256) void wsplit_kernel(
    const float* __restrict__ Wq,
    const float* __restrict__ Wk,
    const float* __restrict__ Wv)
{
    const int idx = blockIdx.x * 256 + threadIdx.x;   // grid 192
    const int mat = idx >> 14;
    const int rem = idx & 16383;
    const float* W = (mat == 0) ? Wq : (mat == 1) ? Wk : Wv;
    const float v = W[rem];
    const uint32_t h = bf2(v, 0.f) & 0xffffu;
    const float vh = __uint_as_float(h << 16);
    const uint32_t l = bf2(v - vh, 0.f) & 0xffffu;
    g_Wh[idx] = (unsigned short)h;
    g_Wl[idx] = (unsigned short)l;
}

// ---------------------------------------------------------------------------
// Kernel 1: QKV projection on tensor cores (bf16x3 split).
// grid = 128 (128 y-rows each), block = 256 (8 warps x 16 rows).
// Per K-chunk of 64: y fp32 tile split inline to bf16 hi/lo smem; W tiles
// cp.async'd from the pre-split arrays.  All 3 outputs accumulated at once.
// SMEM: yh 16K | yl 16K | 6 x Wtile 8K = 80K.
// ---------------------------------------------------------------------------
#define QSM_YH 0
#define QSM_YL 16384
#define QSM_W  32768          /* + (mat*2 + half)*8192 */
#define QSM_TOTAL 81920

__global__ __launch_bounds__(256, 1) void qkv_kernel(
    const float* __restrict__ y)
{
    extern __shared__ char smem[];
    const uint32_t SB = smem_u32(smem);

    const int tid  = threadIdx.x;
    const int lane = tid & 31;
    const int w    = tid >> 5;
    const int r0   = blockIdx.x * 128;

    const int lrow   = lane & 15;
    const int lchunk = lane >> 4;

    float acc[3][8][4];
#pragma unroll
    for (int mat = 0; mat < 3; mat++)
#pragma unroll
        for (int n = 0; n < 8; n++)
#pragma unroll
            for (int e = 0; e < 4; e++) acc[mat][n][e] = 0.f;

    for (int kt = 0; kt < 4; kt++) {
        __syncthreads();   // smem reuse safe across chunks

        // ---- W tiles via cp.async (bf16, pre-split) ----
#pragma unroll
        for (int arr = 0; arr < 6; arr++) {
            const int mat = arr >> 1, half = arr & 1;
            const unsigned short* src = (half ? g_Wl : g_Wh)
                + mat * (NINN * DD) + kt * 64 * DD;
#pragma unroll
            for (int u = 0; u < 2; u++) {
                const int i = tid + u * 256;              // 512 16B chunks
                const int r = i >> 3, g = i & 7;
                CP16(SB + QSM_W + arr * 8192 + swoff(r, g),
                     (const char*)src + r * 128 + g * 16);
            }
        }
        CP_COMMIT();

        // ---- y tile: fp32 load + inline hi/lo split ----
#pragma unroll
        for (int u = 0; u < 4; u++) {
            const int i = tid + u * 256;                  // 1024 8-float chunks
            const int r = i >> 3, g = i & 7;
            const float* src = y + (size_t)(r0 + r) * NINN + kt * 64 + g * 8;
            const float4 a = *(const float4*)(src);
            const float4 c = *(const float4*)(src + 4);
            uint4 hv, lv;
            split_pair(a.x, a.y, hv.x, lv.x);
            split_pair(a.z, a.w, hv.y, lv.y);
            split_pair(c.x, c.y, hv.z, lv.z);
            split_pair(c.z, c.w, hv.w, lv.w);
            const uint32_t sw = swoff(r, g);
            *(uint4*)(smem + QSM_YH + sw) = hv;
            *(uint4*)(smem + QSM_YL + sw) = lv;
        }
        CP_WAIT0();
        __syncthreads();

        // ---- A fragments (this warp's 16 rows, 64 k) ----
        uint32_t Ah[4][4], Al[4][4];
#pragma unroll
        for (int kc = 0; kc < 4; kc++) {
            ldm4(Ah[kc], SB + QSM_YH + swoff(w * 16 + lrow, 2 * kc + lchunk));
            ldm4(Al[kc], SB + QSM_YL + swoff(w * 16 + lrow, 2 * kc + lchunk));
        }

        // ---- acc += Yh Wh + Yl Wh + Yh Wl  for all 3 matrices ----
#pragma unroll
        for (int mat = 0; mat < 3; mat++) {
            const uint32_t WH = SB + QSM_W + (mat * 2) * 8192;
            const uint32_t WL = WH + 8192;
#pragma unroll
            for (int kc = 0; kc < 4; kc++) {
#pragma unroll
                for (int dt = 0; dt < 4; dt++) {
                    uint32_t bh[4];
                    ldm4t(bh, WH + swoff(kc * 16 + lrow, 2 * dt + lchunk));
                    mma_bf16(acc[mat][2 * dt],     Ah[kc], bh[0], bh[1]);
                    mma_bf16(acc[mat][2 * dt + 1], Ah[kc], bh[2], bh[3]);
                    mma_bf16(acc[mat][2 * dt],     Al[kc], bh[0], bh[1]);
                    mma_bf16(acc[mat][2 * dt + 1], Al[kc], bh[2], bh[3]);
                    uint32_t bl[4];
                    ldm4t(bl, WL + swoff(kc * 16 + lrow, 2 * dt + lchunk));
                    mma_bf16(acc[mat][2 * dt],     Ah[kc], bl[0], bl[1]);
                    mma_bf16(acc[mat][2 * dt + 1], Ah[kc], bl[2], bl[3]);
                }
            }
        }
    }

    // ---- epilogue: split accumulators -> bf16 hi/lo global ----
    const int row_lo = r0 + w * 16 + (lane >> 2);
    const int row_hi = row_lo + 8;
    const int col    = (lane & 3) * 2;
#pragma unroll
    for (int mat = 0; mat < 3; mat++) {
        unsigned short* Oh = (mat == 0) ? g_Qh : (mat == 1) ? g_Kh : g_Vh;
        unsigned short* Ol = (mat == 0) ? g_Ql : (mat == 1) ? g_Kl : g_Vl;
#pragma unroll
        for (int n = 0; n < 8; n++) {
            uint32_t h, l;
            split_pair(acc[mat][n][0], acc[mat][n][1], h, l);
            *(uint32_t*)&Oh[(size_t)row_lo * DD + n * 8 + col] = h;
            *(uint32_t*)&Ol[(size_t)row_lo * DD + n * 8 + col] = l;
            split_pair(acc[mat][n][2], acc[mat][n][3], h, l);
            *(uint32_t*)&Oh[(size_t)row_hi * DD + n * 8 + col] = h;
            *(uint32_t*)&Ol[(size_t)row_hi * DD + n * 8 + col] = l;
        }
    }
}

// ---------------------------------------------------------------------------
// Kernel 2: mma.sync bf16x3 causal flash attention, balanced split-K pairs.
// grid = 128: blockIdx -> (b = &3, pair = (>>2)>>1, role = (>>2)&1).
//   role 0: q-tile (31-pair), k-tiles [0,33)            -> partial 0
//   role 1: q-tile (pair) full -> direct; q-tile (31-pair), k-tiles [33, 64-2p) -> partial 1
// Every CTA does exactly 33 k-tile units.
// SMEM: Qh 16K | Ql 16K | 2 x {Kh 8K | Kl 8K | Vh 8K | Vl 8K} = 96K.
// ---------------------------------------------------------------------------
#define SM_QH 0
#define SM_QL 16384
#define SM_KV 32768
#define SM_TOTAL 98304

__device__ __forceinline__ void load_kv(uint32_t SB, int buf, int b, int kbase, int tid) {
    const size_t off = (size_t)(b * TT + kbase) * DD;
    const char* srcs[4] = { (const char*)(g_Kh + off), (const char*)(g_Kl + off),
                            (const char*)(g_Vh + off), (const char*)(g_Vl + off) };
    const uint32_t base = SB + SM_KV + buf * 32768;
#pragma unroll
    for (int arr = 0; arr < 4; arr++)
#pragma unroll
        for (int u = 0; u < 2; u++) {
            const int i = tid + u * 256;
            const int r = i >> 3, g = i & 7;
            CP16(base + arr * 8192 + swoff(r, g), srcs[arr] + r * 128 + g * 16);
        }
}

__device__ __forceinline__ void run_segment(
    uint32_t SB, float* __restrict__ out,
    int b, int pairi, int qtile, int t0, int t1, int partIdx)
{
    const int tid  = threadIdx.x;
    const int lane = tid & 31;
    const int w    = tid >> 5;
    const int q0   = qtile * 128;

    const int lrow   = lane & 15;
    const int lchunk = lane >> 4;
    const int rlo    = w * 16 + (lane >> 2);   // row within tile
    const int rhi    = rlo + 8;
    const int rlo_g  = q0 + rlo;
    const int rhi_g  = q0 + rhi;

    // ---- prologue: Q hi/lo + first K/V buffer ----
    {
        const size_t off = (size_t)(b * TT + q0) * DD;
        const char* qh = (const char*)(g_Qh + off);
        const char* ql = (const char*)(g_Ql + off);
#pragma unroll
        for (int u = 0; u < 4; u++) {
            const int i = tid + u * 256;
            const int r = i >> 3, g = i & 7;
            CP16(SB + SM_QH + swoff(r, g), qh + r * 128 + g * 16);
            CP16(SB + SM_QL + swoff(r, g), ql + r * 128 + g * 16);
        }
        load_kv(SB, 0, b, t0 * 64, tid);
        CP_COMMIT();
        CP_WAIT0();
        __syncthreads();
    }

    uint32_t Ah[4][4], Al[4][4];
#pragma unroll
    for (int kc = 0; kc < 4; kc++) {
        ldm4(Ah[kc], SB + SM_QH + swoff(w * 16 + lrow, 2 * kc + lchunk));
        ldm4(Al[kc], SB + SM_QL + swoff(w * 16 + lrow, 2 * kc + lchunk));
    }

    float O[8][4];
#pragma unroll
    for (int n = 0; n < 8; n++)
#pragma unroll
        for (int e = 0; e < 4; e++) O[n][e] = 0.f;
    float m_lo = -1e30f, m_hi = -1e30f, l_lo = 0.f, l_hi = 0.f;

    for (int t = t0; t < t1; t++) {
        const int buf = (t - t0) & 1;
        const uint32_t KB = SB + SM_KV + buf * 32768;
        if (t + 1 < t1) { load_kv(SB, buf ^ 1, b, (t + 1) * 64, tid); CP_COMMIT(); }

        // ---- S = Qh Kh^T + Ql Kh^T + Qh Kl^T ----
        float S[8][4];
#pragma unroll
        for (int n = 0; n < 8; n++)
#pragma unroll
            for (int e = 0; e < 4; e++) S[n][e] = 0.f;

#pragma unroll
        for (int kc = 0; kc < 4; kc++) {
            uint32_t kh[4][4], kl[4][4];
#pragma unroll
            for (int jt = 0; jt < 4; jt++)
                ldm4(kh[jt], KB + swoff(jt * 16 + lrow, 2 * kc + lchunk));
#pragma unroll
            for (int jt = 0; jt < 4; jt++) {
                mma_bf16(S[2 * jt],     Ah[kc], kh[jt][0], kh[jt][2]);
                mma_bf16(S[2 * jt + 1], Ah[kc], kh[jt][1], kh[jt][3]);
            }
#pragma unroll
            for (int jt = 0; jt < 4; jt++) {
                mma_bf16(S[2 * jt],     Al[kc], kh[jt][0], kh[jt][2]);
                mma_bf16(S[2 * jt + 1], Al[kc], kh[jt][1], kh[jt][3]);
            }
#pragma unroll
            for (int jt = 0; jt < 4; jt++)
                ldm4(kl[jt], KB + 8192 + swoff(jt * 16 + lrow, 2 * kc + lchunk));
#pragma unroll
            for (int jt = 0; jt < 4; jt++) {
                mma_bf16(S[2 * jt],     Ah[kc], kl[jt][0], kl[jt][2]);
                mma_bf16(S[2 * jt + 1], Ah[kc], kl[jt][1], kl[jt][3]);
            }
        }

        // ---- online softmax in the exp2 domain ----
        const int kbase = t * 64;
        const bool tmask = (kbase + 63 > q0 + w * 16);
        float mx_lo = -1e30f, mx_hi = -1e30f;
#pragma unroll
        for (int n = 0; n < 8; n++) {
#pragma unroll
            for (int e = 0; e < 4; e++) {
                float v = S[n][e] * SCALE2;
                if (tmask) {
                    const int j = kbase + n * 8 + (lane & 3) * 2 + (e & 1);
                    const int r = (e < 2) ? rlo_g : rhi_g;
                    if (j > r) v = -1e30f;
                }
                S[n][e] = v;
            }
            mx_lo = fmaxf(mx_lo, fmaxf(S[n][0], S[n][1]));
            mx_hi = fmaxf(mx_hi, fmaxf(S[n][2], S[n][3]));
        }
        mx_lo = fmaxf(mx_lo, __shfl_xor_sync(0xffffffffu, mx_lo, 1));
        mx_lo = fmaxf(mx_lo, __shfl_xor_sync(0xffffffffu, mx_lo, 2));
        mx_hi = fmaxf(mx_hi, __shfl_xor_sync(0xffffffffu, mx_hi, 1));
        mx_hi = fmaxf(mx_hi, __shfl_xor_sync(0xffffffffu, mx_hi, 2));

        const float mn_lo = fmaxf(m_lo, mx_lo);
        const float mn_hi = fmaxf(m_hi, mx_hi);
        const float corr_lo = ex2(m_lo - mn_lo);
        const float corr_hi = ex2(m_hi - mn_hi);
        m_lo = mn_lo; m_hi = mn_hi;

        float ls_lo = 0.f, ls_hi = 0.f;
#pragma unroll
        for (int n = 0; n < 8; n++) {
            S[n][0] = ex2(S[n][0] - mn_lo);
            S[n][1] = ex2(S[n][1] - mn_lo);
            S[n][2] = ex2(S[n][2] - mn_hi);
            S[n][3] = ex2(S[n][3] - mn_hi);
            ls_lo += S[n][0] + S[n][1];
            ls_hi += S[n][2] + S[n][3];
        }
        ls_lo += __shfl_xor_sync(0xffffffffu, ls_lo, 1);
        ls_lo += __shfl_xor_sync(0xffffffffu, ls_lo, 2);
        ls_hi += __shfl_xor_sync(0xffffffffu, ls_hi, 1);
        ls_hi += __shfl_xor_sync(0xffffffffu, ls_hi, 2);
        l_lo = l_lo * corr_lo + ls_lo;
        l_hi = l_hi * corr_hi + ls_hi;

#pragma unroll
        for (int n = 0; n < 8; n++) {
            O[n][0] *= corr_lo; O[n][1] *= corr_lo;
            O[n][2] *= corr_hi; O[n][3] *= corr_hi;
        }

        // ---- P hi/lo A-fragments straight from S registers ----
        uint32_t ph[4][4], pl[4][4];
#pragma unroll
        for (int kc = 0; kc < 4; kc++) {
            split_pair(S[2 * kc][0],     S[2 * kc][1],     ph[kc][0], pl[kc][0]);
            split_pair(S[2 * kc][2],     S[2 * kc][3],     ph[kc][1], pl[kc][1]);
            split_pair(S[2 * kc + 1][0], S[2 * kc + 1][1], ph[kc][2], pl[kc][2]);
            split_pair(S[2 * kc + 1][2], S[2 * kc + 1][3], ph[kc][3], pl[kc][3]);
        }

        // ---- O += Ph Vh + Pl Vh + Ph Vl ----
        const uint32_t VB = KB + 16384;
#pragma unroll
        for (int kc = 0; kc < 4; kc++) {
            uint32_t vh[4][4], vl[4][4];
#pragma unroll
            for (int dt = 0; dt < 4; dt++)
                ldm4t(vh[dt], VB + swoff(kc * 16 + lrow, 2 * dt + lchunk));
#pragma unroll
            for (int dt = 0; dt < 4; dt++) {
                mma_bf16(O[2 * dt],     ph[kc], vh[dt][0], vh[dt][1]);
                mma_bf16(O[2 * dt + 1], ph[kc], vh[dt][2], vh[dt][3]);
            }
#pragma unroll
            for (int dt = 0; dt < 4; dt++) {
                mma_bf16(O[2 * dt],     pl[kc], vh[dt][0], vh[dt][1]);
                mma_bf16(O[2 * dt + 1], pl[kc], vh[dt][2], vh[dt][3]);
            }
#pragma unroll
            for (int dt = 0; dt < 4; dt++)
                ldm4t(vl[dt], VB + 8192 + swoff(kc * 16 + lrow, 2 * dt + lchunk));
#pragma unroll
            for (int dt = 0; dt < 4; dt++) {
                mma_bf16(O[2 * dt],     ph[kc], vl[dt][0], vl[dt][1]);
                mma_bf16(O[2 * dt + 1], ph[kc], vl[dt][2], vl[dt][3]);
            }
        }

        CP_WAIT0();
        __syncthreads();
    }

    // ---- segment epilogue ----
    if (partIdx < 0) {
        const float il_lo = 1.f / l_lo;
        const float il_hi = 1.f / l_hi;
        float* orow_lo = out + (size_t)(b * TT + rlo_g) * DD + (lane & 3) * 2;
        float* orow_hi = out + (size_t)(b * TT + rhi_g) * DD + (lane & 3) * 2;
#pragma unroll
        for (int n = 0; n < 8; n++) {
            float2 v0, v1;
            v0.x = O[n][0] * il_lo; v0.y = O[n][1] * il_lo;
            v1.x = O[n][2] * il_hi; v1.y = O[n][3] * il_hi;
            *(float2*)(orow_lo + n * 8) = v0;
            *(float2*)(orow_hi + n * 8) = v1;
        }
    } else {
        float* Op = &g_Op[partIdx][b][pairi][0][0];
        const int col = (lane & 3) * 2;
#pragma unroll
        for (int n = 0; n < 8; n++) {
            *(float2*)&Op[rlo * 64 + n * 8 + col] = make_float2(O[n][0], O[n][1]);
            *(float2*)&Op[rhi * 64 + n * 8 + col] = make_float2(O[n][2], O[n][3]);
        }
        if ((lane & 3) == 0) {
            g_Om[partIdx][b][pairi][rlo] = m_lo;
            g_Ol[partIdx][b][pairi][rlo] = l_lo;
            g_Om[partIdx][b][pairi][rhi] = m_hi;
            g_Ol[partIdx][b][pairi][rhi] = l_hi;
        }
    }
}

__global__ __launch_bounds__(256) void attn_kernel(float* __restrict__ out)
{
    extern __shared__ char smem[];
    const uint32_t SB = smem_u32(smem);

    const int bi    = blockIdx.x;
    const int b     = bi & 3;
    const int pi    = bi >> 2;        // 0..31
    const int pairi = pi >> 1;        // 0..15
    const int role  = pi & 1;

    const int qa = 31 - pairi;        // split q-tile
    if (role == 0) {
        run_segment(SB, out, b, pairi, qa, 0, 33, 0);
    } else {
        run_segment(SB, out, b, pairi, pairi, 0, 2 * pairi + 2, -1);
        run_segment(SB, out, b, pairi, qa, 33, 64 - 2 * pairi, 1);
    }
}

// ---------------------------------------------------------------------------
// Kernel 3: merge the two split-K partials per split q-tile.
// grid = 64 (b x pair), block = 128 (one row each).
// ---------------------------------------------------------------------------
__global__ __launch_bounds__(128) void merge_kernel(float* __restrict__ out)
{
    const int blk   = blockIdx.x;
    const int b     = blk & 3;
    const int pairi = blk >> 2;
    const int row   = threadIdx.x;
    const int qa    = 31 - pairi;

    const float m0 = g_Om[0][b][pairi][row];
    const float m1 = g_Om[1][b][pairi][row];
    const float l0 = g_Ol[0][b][pairi][row];
    const float l1 = g_Ol[1][b][pairi][row];
    const float mm = fmaxf(m0, m1);
    const float c0 = ex2(m0 - mm);
    const float c1 = ex2(m1 - mm);
    const float inv = 1.f / (l0 * c0 + l1 * c1);

    const float* O0 = &g_Op[0][b][pairi][row][0];
    const float* O1 = &g_Op[1][b][pairi][row][0];
    float* orow = out + ((size_t)(b * TT + qa * 128 + row)) * DD;
#pragma unroll
    for (int g = 0; g < 16; g++) {
        const float4 a = *(const float4*)&O0[g * 4];
        const float4 c = *(const float4*)&O1[g * 4];
        float4 v;
        v.x = (a.x * c0 + c.x * c1) * inv;
        v.y = (a.y * c0 + c.y * c1) * inv;
        v.z = (a.z * c0 + c.z * c1) * inv;
        v.w = (a.w * c0 + c.w * c1) * inv;
        *(float4*)&orow[g * 4] = v;
    }
}

// ---------------------------------------------------------------------------
extern "C" void kernel_launch(void* const* d_in, const int* in_sizes, int n_in,
                              void* d_out, int out_size)
{
    (void)in_sizes; (void)n_in; (void)out_size;
    const float* y  = (const float*)d_in[0];
    const float* Wq = (const float*)d_in[1];
    const float* Wk = (const float*)d_in[2];
    const float* Wv = (const float*)d_in[3];

    wsplit_kernel<<<192, 256>>>(Wq, Wk, Wv);

    cudaFuncSetAttribute(qkv_kernel,
                         cudaFuncAttributeMaxDynamicSharedMemorySize, QSM_TOTAL);
    qkv_kernel<<<128, 256, QSM_TOTAL>>>(y);

    cudaFuncSetAttribute(attn_kernel,
                         cudaFuncAttributeMaxDynamicSharedMemorySize, SM_TOTAL);
    attn_kernel<<<128, 256, SM_TOTAL>>>((float*)d_out);

    merge_kernel<<<64, 128>>>((float*)d_out);
}